// round 12
// baseline (speedup 1.0000x reference)
#include <cuda_runtime.h>
#include <cuda_fp16.h>
#include <cstdint>

// ---------------------------------------------------------------------------
// Problem constants
// ---------------------------------------------------------------------------
#define L_DIM 1024
#define B_DIM 32
#define IN_DIM 1024
#define D_DIM 1024
#define M_DIM (L_DIM * B_DIM)      // 32768
#define N_DIM (4 * D_DIM)          // 4096
#define K_DIM IN_DIM               // 1024

// GEMM tiling (fp16 operands), persistent CTAs, 2 CTAs/SM
#define BM 128
#define BN 128
#define BKB 64                     // K per stage
#define NSTG (K_DIM / BKB)         // 16 stages per tile
#define ASTG_B (BM * BKB * 2)      // 16384 B / stage
#define BSTG_B (BN * BKB * 2)      // 16384 B / stage
#define STG_B (ASTG_B + BSTG_B)    // 32768 B
#define NPIPE 3
#define GEMM_SMEM (NPIPE * STG_B)  // 98304 B  -> 2 CTAs/SM
#define NT_M (M_DIM / BM)          // 256
#define NT_N (N_DIM / BN)          // 32
#define NTILES (NT_M * NT_N)       // 8192
#define GRID_P 296                 // 148 SMs x 2 CTAs

// Scratch (device globals; no allocation allowed)
// U stored fp16. 16B unit u = lp*32768 + b*1024 + d  (lp = l/2):
//   halves [g0l0 g1l0 g0l1 g1l1 g2l0 g3l0 g2l1 g3l1]
//   i.e. half idx = u*8 + (g>>1)*4 + (l&1)*2 + (g&1)
__device__ __half g_U16[(size_t)M_DIM * N_DIM];         // 256 MB
__device__ __half g_Ap[(size_t)M_DIM * K_DIM];          // 64 MB  fragment-ordered x
__device__ __half g_Bp[(size_t)N_DIM * K_DIM];          // 8 MB   fragment-ordered W

// ---------------------------------------------------------------------------
// helpers
// ---------------------------------------------------------------------------
__device__ __forceinline__ uint32_t smem_u32(const void* p) {
    uint32_t a;
    asm("{ .reg .u64 t; cvta.to.shared.u64 t, %1; cvt.u32.u64 %0, t; }"
        : "=r"(a) : "l"(p));
    return a;
}
__device__ __forceinline__ void cp16(uint32_t s, const void* g) {
    asm volatile("cp.async.cg.shared.global [%0], [%1], 16;" :: "r"(s), "l"(g));
}
__device__ __forceinline__ uint32_t h2_u32(__half2 h) {
    uint32_t u;
    memcpy(&u, &h, 4);
    return u;
}

#define LDS128(r0, r1, r2, r3, addr)                                           \
    asm volatile("ld.shared.v4.b32 {%0,%1,%2,%3}, [%4];"                       \
                 : "=r"(r0), "=r"(r1), "=r"(r2), "=r"(r3) : "r"(addr))

#define MMA_F16(d, a, b0, b1)                                                  \
    asm volatile(                                                              \
        "mma.sync.aligned.m16n8k16.row.col.f32.f16.f16.f32 "                   \
        "{%0,%1,%2,%3}, {%4,%5,%6,%7}, {%8,%9}, {%0,%1,%2,%3};"                \
        : "+f"((d)[0]), "+f"((d)[1]), "+f"((d)[2]), "+f"((d)[3])               \
        : "r"((a)[0]), "r"((a)[1]), "r"((a)[2]), "r"((a)[3]),                  \
          "r"(b0), "r"(b1))

// ---------------------------------------------------------------------------
// Prep A: x (fp32) -> g_Ap, fp16, m16n8k16 A-fragment order.
// ---------------------------------------------------------------------------
__global__ __launch_bounds__(256) void prep_x_kernel(
    const float* __restrict__ x, __half* __restrict__ Ap)
{
    int T = blockIdx.x * 8 + (threadIdx.x >> 5);
    int t = threadIdx.x & 31;
    int kt    = T & 1;
    int mt    = (T >> 1) & 7;
    int k_blk = (T >> 4) & 31;
    int m_blk = T >> 9;
    int r = m_blk * BM + mt * 16 + (t >> 2);
    int c = k_blk * 32 + kt * 16 + (t & 3) * 2;
    const float* xr = x + (size_t)r * K_DIM + c;
    float2 v0 = *(const float2*)xr;
    float2 v1 = *(const float2*)(xr + (size_t)8 * K_DIM);
    float2 v2 = *(const float2*)(xr + 8);
    float2 v3 = *(const float2*)(xr + (size_t)8 * K_DIM + 8);
    uint4 o;
    o.x = h2_u32(__floats2half2_rn(v0.x, v0.y));
    o.y = h2_u32(__floats2half2_rn(v1.x, v1.y));
    o.z = h2_u32(__floats2half2_rn(v2.x, v2.y));
    o.w = h2_u32(__floats2half2_rn(v3.x, v3.y));
    ((uint4*)Ap)[(size_t)T * 32 + t] = o;
}

// ---------------------------------------------------------------------------
// Prep B: W [K][N] fp32 -> g_Bp, fp16, m16n8k16 B-fragment order (col-major).
// ---------------------------------------------------------------------------
__global__ __launch_bounds__(256) void prep_W_kernel(
    const float* __restrict__ W, __half* __restrict__ Bp)
{
    int T = blockIdx.x * 8 + (threadIdx.x >> 5);
    int t = threadIdx.x & 31;
    int kt    = T & 1;
    int np    = (T >> 1) & 7;
    int k_blk = (T >> 4) & 31;
    int n_blk = T >> 9;
    int k = k_blk * 32 + kt * 16 + (t & 3) * 2;
    int n = n_blk * BN + np * 16 + (t >> 2);
    const float* wp = W + (size_t)k * N_DIM + n;
    float w0  = wp[0];
    float w1  = wp[N_DIM];
    float w8  = wp[(size_t)8 * N_DIM];
    float w9  = wp[(size_t)9 * N_DIM];
    float w0b = wp[8];
    float w1b = wp[N_DIM + 8];
    float w8b = wp[(size_t)8 * N_DIM + 8];
    float w9b = wp[(size_t)9 * N_DIM + 8];
    uint4 o;
    o.x = h2_u32(__floats2half2_rn(w0, w1));
    o.y = h2_u32(__floats2half2_rn(w8, w9));
    o.z = h2_u32(__floats2half2_rn(w0b, w1b));
    o.w = h2_u32(__floats2half2_rn(w8b, w9b));
    ((uint4*)Bp)[(size_t)T * 32 + t] = o;
}

// ---------------------------------------------------------------------------
// Persistent GEMM: U16 = Ap . Bp^T via mma.sync m16n8k16 fp16 (fp32 accum).
// 296 CTAs, each walks tiles tile += 296 with one continuous cp.async
// pipeline (load cursor crosses tile boundaries; empty commit_groups keep
// wait_group accounting exact past the end).
// ---------------------------------------------------------------------------
__global__ __launch_bounds__(256, 2) void gemm_f16_mma_kernel(
    const __half* __restrict__ Ap,
    const __half* __restrict__ Bp,
    __half* __restrict__ U16)
{
    extern __shared__ __align__(16) char smem[];
    const uint32_t sbase = smem_u32(smem);
    const int tid  = threadIdx.x;
    const int wid  = tid >> 5;
    const int lane = tid & 31;
    const int wr   = wid >> 2;     // 0..1: 64-row slab
    const int wc   = wid & 3;      // 0..3: 32-col slab

    const char* gAb = (const char*)Ap;
    const char* gBb = (const char*)Bp;

    // load cursor (global across tiles)
    int lt = blockIdx.x;   // tile being loaded
    int lk = 0;            // k-stage within that tile
    int lbuf = 0;          // smem buffer index

    auto issue = [&]() {
        if (lt < NTILES) {
            int mbL = lt >> 5;
            int nbL = lt & 31;
            uint32_t sa = sbase + (uint32_t)lbuf * STG_B;
            const char* ga = gAb + ((size_t)mbL * NSTG + lk) * ASTG_B;
            const char* gb = gBb + ((size_t)nbL * NSTG + lk) * BSTG_B;
#pragma unroll
            for (int i = 0; i < 4; i++)
                cp16(sa + tid * 16 + i * 4096, ga + tid * 16 + i * 4096);
            uint32_t sb = sa + ASTG_B;
#pragma unroll
            for (int i = 0; i < 4; i++)
                cp16(sb + tid * 16 + i * 4096, gb + tid * 16 + i * 4096);
        }
        asm volatile("cp.async.commit_group;" ::: "memory");
        if (++lbuf == NPIPE) lbuf = 0;
        if (++lk == NSTG) { lk = 0; lt += GRID_P; }
    };

    issue();
    issue();

    int cbuf = 0;
    uint32_t afr[2][4][4];
    uint32_t bfr[2][2][4];
    const uint32_t aoff = (uint32_t)((wr * 4) * 2 * 32 + lane) * 16;
    const uint32_t boff = (uint32_t)((wc * 2) * 2 * 32 + lane) * 16;

    for (int tile = blockIdx.x; tile < NTILES; tile += GRID_P) {
        const int mb = tile >> 5;
        const int nb = tile & 31;

        float acc[4][4][4] = {};

        for (int kb = 0; kb < NSTG; kb++) {
            asm volatile("cp.async.wait_group 1;" ::: "memory");
            __syncthreads();
            issue();

            uint32_t sstage = sbase + (uint32_t)cbuf * STG_B;

            auto load_frags = [&](int kk, int buf) {
                uint32_t sa = sstage + (uint32_t)(kk >> 1) * 8192 + aoff
                            + (uint32_t)(kk & 1) * 512;
                uint32_t sb = sstage + ASTG_B + (uint32_t)(kk >> 1) * 8192 + boff
                            + (uint32_t)(kk & 1) * 512;
#pragma unroll
                for (int mi = 0; mi < 4; mi++)
                    LDS128(afr[buf][mi][0], afr[buf][mi][1],
                           afr[buf][mi][2], afr[buf][mi][3], sa + mi * 1024);
#pragma unroll
                for (int pi = 0; pi < 2; pi++)
                    LDS128(bfr[buf][pi][0], bfr[buf][pi][1],
                           bfr[buf][pi][2], bfr[buf][pi][3], sb + pi * 1024);
            };

            load_frags(0, 0);
#pragma unroll
            for (int kk = 0; kk < 4; kk++) {
                int cur = kk & 1;
                if (kk < 3) load_frags(kk + 1, cur ^ 1);
#pragma unroll
                for (int mi = 0; mi < 4; mi++)
#pragma unroll
                    for (int pi = 0; pi < 2; pi++) {
                        MMA_F16(acc[mi][pi * 2],     afr[cur][mi],
                                bfr[cur][pi][0], bfr[cur][pi][1]);
                        MMA_F16(acc[mi][pi * 2 + 1], afr[cur][mi],
                                bfr[cur][pi][2], bfr[cur][pi][3]);
                    }
            }
            if (++cbuf == NPIPE) cbuf = 0;
        }

        // Epilogue: STG.64 per (mi,half,ni): thread packs (l even, l odd)
        // for its 2 gates. unit u = lp*32768 + b*1024 + d; byte off in unit:
        //   (g>>1)*8  (+4 for l odd half, handled by the uint2).
        {
            const int n  = nb * BN + wc * 32 + (lane & 3) * 2;  // +ni*8
            const int m0 = mb * BM + wr * 64 + (lane >> 2);
            const uint32_t goff = (uint32_t)(((n & 3) >> 1) * 8);
#pragma unroll
            for (int mi = 0; mi < 2; mi++) {
#pragma unroll
                for (int half = 0; half < 2; half++) {
                    int m  = m0 + mi * 16 + half * 8;   // even-l row
                    int l0 = m >> 5;                    // even l of the pair
                    int b  = m & 31;
                    size_t ubase = (size_t)(l0 >> 1) * 32768 + (size_t)b * 1024;
#pragma unroll
                    for (int ni = 0; ni < 4; ni++) {
                        int d = (n + ni * 8) >> 2;
                        uint2 v;
                        v.x = h2_u32(__floats2half2_rn(acc[mi][ni][half * 2],
                                                       acc[mi][ni][half * 2 + 1]));
                        v.y = h2_u32(__floats2half2_rn(acc[mi + 2][ni][half * 2],
                                                       acc[mi + 2][ni][half * 2 + 1]));
                        *(uint2*)((char*)U16 + (ubase + d) * 16 + goff) = v;
                    }
                }
            }
        }
    }
}

// ---------------------------------------------------------------------------
// SRU scan: one thread per (b,d) lane; HW tanh.approx for all gates.
// U16 unit = [g0l0 g1l0 g0l1 g1l1 g2l0 g3l0 g2l1 g3l1]; 16-deep prefetch.
// ---------------------------------------------------------------------------
__device__ __forceinline__ float tanh_fast(float x) {
    float r;
    asm("tanh.approx.f32 %0, %1;" : "=f"(r) : "f"(x));
    return r;
}
__device__ __forceinline__ float sigmoid_fast(float z) {
    return fmaf(tanh_fast(z * 0.5f), 0.5f, 0.5f);
}

__global__ __launch_bounds__(128) void sru_scan_kernel(
    const __half* __restrict__ U16,
    const float* __restrict__ c0,
    const float* __restrict__ V,
    const float* __restrict__ bias,
    float* __restrict__ h_out,
    float* __restrict__ c_out)
{
    const int t = blockIdx.x * blockDim.x + threadIdx.x;   // 0..32767 = b*1024+d
    const int d = t & (D_DIM - 1);

    const float vf = V[d];
    const float vr = V[D_DIM + d];
    const float bf = bias[d];
    const float br = bias[D_DIM + d];
    float c = c0[t];

    const uint4* __restrict__ Up = (const uint4*)U16 + t;  // stride 32768 per l-pair
    float* __restrict__ hp = h_out + t;

    uint4 buf[16];
#pragma unroll
    for (int j = 0; j < 16; j++) buf[j] = Up[(size_t)j * (B_DIM * D_DIM)];

    for (int lp = 0; lp < L_DIM / 2; lp += 16) {
        uint4 cur[16];
#pragma unroll
        for (int j = 0; j < 16; j++) cur[j] = buf[j];
        if (lp + 16 < L_DIM / 2) {
#pragma unroll
            for (int j = 0; j < 16; j++)
                buf[j] = Up[(size_t)(lp + 16 + j) * (B_DIM * D_DIM)];
        }
#pragma unroll
        for (int j = 0; j < 16; j++) {
            const __half2* hh = (const __half2*)&cur[j];
#pragma unroll
            for (int s = 0; s < 2; s++) {
                float2 g01 = __half22float2(hh[s]);       // {u0,u1} of l = 2lp+s
                float2 g23 = __half22float2(hh[2 + s]);   // {u2,u3}
                float f = sigmoid_fast(g01.y + c * vf + bf);
                float r = sigmoid_fast(g23.x + c * vr + br);
                c = g01.x + (c - g01.x) * f;
                float h = (tanh_fast(c) - g23.y) * r + g23.y;
                hp[(size_t)((lp + j) * 2 + s) * (B_DIM * D_DIM)] = h;
            }
        }
    }

    if (c_out) c_out[t] = c;
}

// ---------------------------------------------------------------------------
// Launch
// ---------------------------------------------------------------------------
extern "C" void kernel_launch(void* const* d_in, const int* in_sizes, int n_in,
                              void* d_out, int out_size)
{
    const float* x    = (const float*)d_in[0];   // (L,B,IN)
    const float* c0   = (const float*)d_in[1];   // (B,D)
    const float* W    = (const float*)d_in[2];   // (IN,4D)
    const float* V    = (const float*)d_in[3];   // (2D)
    const float* bias = (const float*)d_in[4];   // (2D)
    float* out = (float*)d_out;

    __half *U16 = nullptr, *Ap = nullptr, *Bp = nullptr;
    cudaGetSymbolAddress((void**)&U16, g_U16);
    cudaGetSymbolAddress((void**)&Ap, g_Ap);
    cudaGetSymbolAddress((void**)&Bp, g_Bp);

    cudaFuncSetAttribute(gemm_f16_mma_kernel,
                         cudaFuncAttributeMaxDynamicSharedMemorySize, GEMM_SMEM);

    prep_x_kernel<<<16384, 256>>>(x, Ap);
    prep_W_kernel<<<2048, 256>>>(W, Bp);

    gemm_f16_mma_kernel<<<GRID_P, 256, GEMM_SMEM>>>(Ap, Bp, U16);

    const size_t LBD = (size_t)L_DIM * B_DIM * D_DIM;
    float* c_out = ((size_t)out_size > LBD) ? (out + LBD) : nullptr;
    sru_scan_kernel<<<(B_DIM * D_DIM) / 128, 128>>>(U16, c0, V, bias, out, c_out);
}

// round 13
// speedup vs baseline: 1.0430x; 1.0430x over previous
#include <cuda_runtime.h>
#include <cuda_fp16.h>
#include <cstdint>

// ---------------------------------------------------------------------------
// Problem constants
// ---------------------------------------------------------------------------
#define L_DIM 1024
#define B_DIM 32
#define IN_DIM 1024
#define D_DIM 1024
#define M_DIM (L_DIM * B_DIM)      // 32768
#define N_DIM (4 * D_DIM)          // 4096
#define K_DIM IN_DIM               // 1024

// GEMM tiling (fp16 operands), 2 CTAs/SM
#define BM 128
#define BN 128
#define BKB 64                     // K per stage
#define NSTG (K_DIM / BKB)         // 16 stages
#define ASTG_B (BM * BKB * 2)      // 16384 B / stage
#define BSTG_B (BN * BKB * 2)      // 16384 B / stage
#define STG_B (ASTG_B + BSTG_B)    // 32768 B
#define NPIPE 3
#define GEMM_SMEM (NPIPE * STG_B)  // 98304 B  -> 2 CTAs/SM

// Scratch (device globals; no allocation allowed)
// U stored fp16. 16B unit u = lp*32768 + b*1024 + d  (lp = l/2):
//   halves [g0l0 g1l0 g0l1 g1l1 g2l0 g3l0 g2l1 g3l1]
__device__ __half g_U16[(size_t)M_DIM * N_DIM];         // 256 MB
__device__ __half g_Ap[(size_t)M_DIM * K_DIM];          // 64 MB  fragment-ordered x
__device__ __half g_Bp[(size_t)N_DIM * K_DIM];          // 8 MB   fragment-ordered W

// ---------------------------------------------------------------------------
// helpers
// ---------------------------------------------------------------------------
__device__ __forceinline__ uint32_t smem_u32(const void* p) {
    uint32_t a;
    asm("{ .reg .u64 t; cvta.to.shared.u64 t, %1; cvt.u32.u64 %0, t; }"
        : "=r"(a) : "l"(p));
    return a;
}
__device__ __forceinline__ void cp16(uint32_t s, const void* g) {
    asm volatile("cp.async.cg.shared.global [%0], [%1], 16;" :: "r"(s), "l"(g));
}
__device__ __forceinline__ uint32_t h2_u32(__half2 h) {
    uint32_t u;
    memcpy(&u, &h, 4);
    return u;
}

#define LDS128(r0, r1, r2, r3, addr)                                           \
    asm volatile("ld.shared.v4.b32 {%0,%1,%2,%3}, [%4];"                       \
                 : "=r"(r0), "=r"(r1), "=r"(r2), "=r"(r3) : "r"(addr))

#define MMA_F16(d, a, b0, b1)                                                  \
    asm volatile(                                                              \
        "mma.sync.aligned.m16n8k16.row.col.f32.f16.f16.f32 "                   \
        "{%0,%1,%2,%3}, {%4,%5,%6,%7}, {%8,%9}, {%0,%1,%2,%3};"                \
        : "+f"((d)[0]), "+f"((d)[1]), "+f"((d)[2]), "+f"((d)[3])               \
        : "r"((a)[0]), "r"((a)[1]), "r"((a)[2]), "r"((a)[3]),                  \
          "r"(b0), "r"(b1))

// ---------------------------------------------------------------------------
// Fused prep: blocks [0,16384) -> A fragments, [16384,18432) -> B fragments.
// ---------------------------------------------------------------------------
__global__ __launch_bounds__(256) void prep_kernel(
    const float* __restrict__ x, const float* __restrict__ W,
    __half* __restrict__ Ap, __half* __restrict__ Bp)
{
    int t = threadIdx.x & 31;
    if (blockIdx.x < 16384) {
        int T = blockIdx.x * 8 + (threadIdx.x >> 5);
        int kt    = T & 1;
        int mt    = (T >> 1) & 7;
        int k_blk = (T >> 4) & 31;
        int m_blk = T >> 9;
        int r = m_blk * BM + mt * 16 + (t >> 2);
        int c = k_blk * 32 + kt * 16 + (t & 3) * 2;
        const float* xr = x + (size_t)r * K_DIM + c;
        float2 v0 = *(const float2*)xr;
        float2 v1 = *(const float2*)(xr + (size_t)8 * K_DIM);
        float2 v2 = *(const float2*)(xr + 8);
        float2 v3 = *(const float2*)(xr + (size_t)8 * K_DIM + 8);
        uint4 o;
        o.x = h2_u32(__floats2half2_rn(v0.x, v0.y));
        o.y = h2_u32(__floats2half2_rn(v1.x, v1.y));
        o.z = h2_u32(__floats2half2_rn(v2.x, v2.y));
        o.w = h2_u32(__floats2half2_rn(v3.x, v3.y));
        ((uint4*)Ap)[(size_t)T * 32 + t] = o;
    } else {
        int T = (blockIdx.x - 16384) * 8 + (threadIdx.x >> 5);
        int kt    = T & 1;
        int np    = (T >> 1) & 7;
        int k_blk = (T >> 4) & 31;
        int n_blk = T >> 9;
        int k = k_blk * 32 + kt * 16 + (t & 3) * 2;
        int n = n_blk * BN + np * 16 + (t >> 2);
        const float* wp = W + (size_t)k * N_DIM + n;
        float w0  = wp[0];
        float w1  = wp[N_DIM];
        float w8  = wp[(size_t)8 * N_DIM];
        float w9  = wp[(size_t)9 * N_DIM];
        float w0b = wp[8];
        float w1b = wp[N_DIM + 8];
        float w8b = wp[(size_t)8 * N_DIM + 8];
        float w9b = wp[(size_t)9 * N_DIM + 8];
        uint4 o;
        o.x = h2_u32(__floats2half2_rn(w0, w1));
        o.y = h2_u32(__floats2half2_rn(w8, w9));
        o.z = h2_u32(__floats2half2_rn(w0b, w1b));
        o.w = h2_u32(__floats2half2_rn(w8b, w9b));
        ((uint4*)Bp)[(size_t)T * 32 + t] = o;
    }
}

// ---------------------------------------------------------------------------
// GEMM: U16 = Ap . Bp^T via mma.sync m16n8k16 fp16 (fp32 accum).
// CTA 128x128, 8 warps (2x4), warp tile 64x32, BK=64, 3-stage cp.async,
// 2 CTAs/SM; fragment loads double-buffered; first frag LDS issued before
// the next stage's cp.async batch.
// ---------------------------------------------------------------------------
__global__ __launch_bounds__(256, 2) void gemm_f16_mma_kernel(
    const __half* __restrict__ Ap,
    const __half* __restrict__ Bp,
    __half* __restrict__ U16)
{
    extern __shared__ __align__(16) char smem[];
    const uint32_t sbase = smem_u32(smem);
    const int tid  = threadIdx.x;
    const int wid  = tid >> 5;
    const int lane = tid & 31;
    const int wr   = wid >> 2;     // 0..1: 64-row slab
    const int wc   = wid & 3;      // 0..3: 32-col slab
    const int mb   = blockIdx.y;
    const int nb   = blockIdx.x;

    const char* gA = (const char*)(Ap) + (size_t)mb * NSTG * ASTG_B;
    const char* gB = (const char*)(Bp) + (size_t)nb * NSTG * BSTG_B;

    auto load_stage = [&](int s) {
        uint32_t sa = sbase + (uint32_t)(s % NPIPE) * STG_B;
        const char* ga = gA + (size_t)s * ASTG_B;
        const char* gb = gB + (size_t)s * BSTG_B;
#pragma unroll
        for (int i = 0; i < 4; i++)
            cp16(sa + tid * 16 + i * 4096, ga + tid * 16 + i * 4096);
        uint32_t sb = sa + ASTG_B;
#pragma unroll
        for (int i = 0; i < 4; i++)
            cp16(sb + tid * 16 + i * 4096, gb + tid * 16 + i * 4096);
        asm volatile("cp.async.commit_group;" ::: "memory");
    };

    load_stage(0);
    load_stage(1);

    float acc[4][4][4] = {};
    uint32_t afr[2][4][4];
    uint32_t bfr[2][2][4];

    const uint32_t aoff = (uint32_t)((wr * 4) * 2 * 32 + lane) * 16;
    const uint32_t boff = (uint32_t)((wc * 2) * 2 * 32 + lane) * 16;

    for (int kb = 0; kb < NSTG; kb++) {
        if (kb < NSTG - 1) asm volatile("cp.async.wait_group 1;" ::: "memory");
        else               asm volatile("cp.async.wait_group 0;" ::: "memory");
        __syncthreads();

        uint32_t sstage = sbase + (uint32_t)(kb % NPIPE) * STG_B;

        auto load_frags = [&](int kk, int buf) {
            uint32_t sa = sstage + (uint32_t)(kk >> 1) * 8192 + aoff
                        + (uint32_t)(kk & 1) * 512;
            uint32_t sb = sstage + ASTG_B + (uint32_t)(kk >> 1) * 8192 + boff
                        + (uint32_t)(kk & 1) * 512;
#pragma unroll
            for (int mi = 0; mi < 4; mi++)
                LDS128(afr[buf][mi][0], afr[buf][mi][1],
                       afr[buf][mi][2], afr[buf][mi][3], sa + mi * 1024);
#pragma unroll
            for (int pi = 0; pi < 2; pi++)
                LDS128(bfr[buf][pi][0], bfr[buf][pi][1],
                       bfr[buf][pi][2], bfr[buf][pi][3], sb + pi * 1024);
        };

        // first fragments first, then the next stage's global loads
        load_frags(0, 0);
        if (kb + 2 < NSTG) load_stage(kb + 2);

#pragma unroll
        for (int kk = 0; kk < 4; kk++) {
            int cur = kk & 1;
            if (kk < 3) load_frags(kk + 1, cur ^ 1);
#pragma unroll
            for (int mi = 0; mi < 4; mi++)
#pragma unroll
                for (int pi = 0; pi < 2; pi++) {
                    MMA_F16(acc[mi][pi * 2],     afr[cur][mi],
                            bfr[cur][pi][0], bfr[cur][pi][1]);
                    MMA_F16(acc[mi][pi * 2 + 1], afr[cur][mi],
                            bfr[cur][pi][2], bfr[cur][pi][3]);
                }
        }
    }

    // Epilogue: STG.64; thread packs its 2 gate values for l-even/odd pair
    // across acc[mi] and acc[mi+2] (rows m and m+32 share the same unit? no:
    // acc rows mi*16 differ by 16 in m -> pack (mi, mi+2): m and m+32 -> same
    // l parity pair (l and l+1) at identical (b,d) -> contiguous uint2.
    {
        const int n  = nb * BN + wc * 32 + (lane & 3) * 2;  // +ni*8
        const int m0 = mb * BM + wr * 64 + (lane >> 2);
        const uint32_t goff = (uint32_t)(((n & 3) >> 1) * 8);
#pragma unroll
        for (int mi = 0; mi < 2; mi++) {
#pragma unroll
            for (int half = 0; half < 2; half++) {
                int m  = m0 + mi * 16 + half * 8;   // even-l row
                int l0 = m >> 5;
                int b  = m & 31;
                size_t ubase = (size_t)(l0 >> 1) * 32768 + (size_t)b * 1024;
#pragma unroll
                for (int ni = 0; ni < 4; ni++) {
                    int d = (n + ni * 8) >> 2;
                    uint2 v;
                    v.x = h2_u32(__floats2half2_rn(acc[mi][ni][half * 2],
                                                   acc[mi][ni][half * 2 + 1]));
                    v.y = h2_u32(__floats2half2_rn(acc[mi + 2][ni][half * 2],
                                                   acc[mi + 2][ni][half * 2 + 1]));
                    *(uint2*)((char*)U16 + (ubase + d) * 16 + goff) = v;
                }
            }
        }
    }
}

// ---------------------------------------------------------------------------
// SRU scan: one thread per (b,d) lane; HW tanh.approx for all gates.
// U16 unit = [g0l0 g1l0 g0l1 g1l1 g2l0 g3l0 g2l1 g3l1]; 16-deep prefetch.
// ---------------------------------------------------------------------------
__device__ __forceinline__ float tanh_fast(float x) {
    float r;
    asm("tanh.approx.f32 %0, %1;" : "=f"(r) : "f"(x));
    return r;
}
__device__ __forceinline__ float sigmoid_fast(float z) {
    return fmaf(tanh_fast(z * 0.5f), 0.5f, 0.5f);
}

__global__ __launch_bounds__(128) void sru_scan_kernel(
    const __half* __restrict__ U16,
    const float* __restrict__ c0,
    const float* __restrict__ V,
    const float* __restrict__ bias,
    float* __restrict__ h_out,
    float* __restrict__ c_out)
{
    const int t = blockIdx.x * blockDim.x + threadIdx.x;   // 0..32767 = b*1024+d
    const int d = t & (D_DIM - 1);

    const float vf = V[d];
    const float vr = V[D_DIM + d];
    const float bf = bias[d];
    const float br = bias[D_DIM + d];
    float c = c0[t];

    const uint4* __restrict__ Up = (const uint4*)U16 + t;  // stride 32768 per l-pair
    float* __restrict__ hp = h_out + t;

    uint4 buf[16];
#pragma unroll
    for (int j = 0; j < 16; j++) buf[j] = Up[(size_t)j * (B_DIM * D_DIM)];

    for (int lp = 0; lp < L_DIM / 2; lp += 16) {
        uint4 cur[16];
#pragma unroll
        for (int j = 0; j < 16; j++) cur[j] = buf[j];
        if (lp + 16 < L_DIM / 2) {
#pragma unroll
            for (int j = 0; j < 16; j++)
                buf[j] = Up[(size_t)(lp + 16 + j) * (B_DIM * D_DIM)];
        }
#pragma unroll
        for (int j = 0; j < 16; j++) {
            const __half2* hh = (const __half2*)&cur[j];
#pragma unroll
            for (int s = 0; s < 2; s++) {
                float2 g01 = __half22float2(hh[s]);       // {u0,u1} of l = 2lp+s
                float2 g23 = __half22float2(hh[2 + s]);   // {u2,u3}
                float f = sigmoid_fast(g01.y + c * vf + bf);
                float r = sigmoid_fast(g23.x + c * vr + br);
                c = g01.x + (c - g01.x) * f;
                float h = (tanh_fast(c) - g23.y) * r + g23.y;
                hp[(size_t)((lp + j) * 2 + s) * (B_DIM * D_DIM)] = h;
            }
        }
    }

    if (c_out) c_out[t] = c;
}

// ---------------------------------------------------------------------------
// Launch
// ---------------------------------------------------------------------------
extern "C" void kernel_launch(void* const* d_in, const int* in_sizes, int n_in,
                              void* d_out, int out_size)
{
    const float* x    = (const float*)d_in[0];   // (L,B,IN)
    const float* c0   = (const float*)d_in[1];   // (B,D)
    const float* W    = (const float*)d_in[2];   // (IN,4D)
    const float* V    = (const float*)d_in[3];   // (2D)
    const float* bias = (const float*)d_in[4];   // (2D)
    float* out = (float*)d_out;

    __half *U16 = nullptr, *Ap = nullptr, *Bp = nullptr;
    cudaGetSymbolAddress((void**)&U16, g_U16);
    cudaGetSymbolAddress((void**)&Ap, g_Ap);
    cudaGetSymbolAddress((void**)&Bp, g_Bp);

    cudaFuncSetAttribute(gemm_f16_mma_kernel,
                         cudaFuncAttributeMaxDynamicSharedMemorySize, GEMM_SMEM);

    prep_kernel<<<18432, 256>>>(x, W, Ap, Bp);

    gemm_f16_mma_kernel<<<dim3(N_DIM / BN, M_DIM / BM), 256, GEMM_SMEM>>>(
        Ap, Bp, U16);

    const size_t LBD = (size_t)L_DIM * B_DIM * D_DIM;
    float* c_out = ((size_t)out_size > LBD) ? (out + LBD) : nullptr;
    sru_scan_kernel<<<(B_DIM * D_DIM) / 128, 128>>>(U16, c0, V, bias, out, c_out);
}

// round 14
// speedup vs baseline: 1.0708x; 1.0266x over previous
#include <cuda_runtime.h>
#include <cuda_fp16.h>
#include <cstdint>

// ---------------------------------------------------------------------------
// Problem constants
// ---------------------------------------------------------------------------
#define L_DIM 1024
#define B_DIM 32
#define IN_DIM 1024
#define D_DIM 1024
#define M_DIM (L_DIM * B_DIM)      // 32768
#define N_DIM (4 * D_DIM)          // 4096
#define K_DIM IN_DIM               // 1024

// GEMM tiling (fp16 operands), 2 CTAs/SM, 4 warps/CTA, warp tile 64x64
#define BM 128
#define BN 128
#define BKB 64                     // K per stage
#define NSTG (K_DIM / BKB)         // 16 stages
#define ASTG_B (BM * BKB * 2)      // 16384 B / stage
#define BSTG_B (BN * BKB * 2)      // 16384 B / stage
#define STG_B (ASTG_B + BSTG_B)    // 32768 B
#define NPIPE 3
#define GEMM_SMEM (NPIPE * STG_B)  // 98304 B  -> 2 CTAs/SM

// Scratch (device globals; no allocation allowed)
// U stored fp16. 16B unit u = lp*32768 + b*1024 + d  (lp = l/2):
//   halves [g0l0 g1l0 g0l1 g1l1 g2l0 g3l0 g2l1 g3l1]
__device__ __half g_U16[(size_t)M_DIM * N_DIM];         // 256 MB
__device__ __half g_Ap[(size_t)M_DIM * K_DIM];          // 64 MB  fragment-ordered x
__device__ __half g_Bp[(size_t)N_DIM * K_DIM];          // 8 MB   fragment-ordered W

// ---------------------------------------------------------------------------
// helpers
// ---------------------------------------------------------------------------
__device__ __forceinline__ uint32_t smem_u32(const void* p) {
    uint32_t a;
    asm("{ .reg .u64 t; cvta.to.shared.u64 t, %1; cvt.u32.u64 %0, t; }"
        : "=r"(a) : "l"(p));
    return a;
}
__device__ __forceinline__ void cp16(uint32_t s, const void* g) {
    asm volatile("cp.async.cg.shared.global [%0], [%1], 16;" :: "r"(s), "l"(g));
}
__device__ __forceinline__ uint32_t h2_u32(__half2 h) {
    uint32_t u;
    memcpy(&u, &h, 4);
    return u;
}

#define LDS128(r0, r1, r2, r3, addr)                                           \
    asm volatile("ld.shared.v4.b32 {%0,%1,%2,%3}, [%4];"                       \
                 : "=r"(r0), "=r"(r1), "=r"(r2), "=r"(r3) : "r"(addr))

#define MMA_F16(d, a, b0, b1)                                                  \
    asm volatile(                                                              \
        "mma.sync.aligned.m16n8k16.row.col.f32.f16.f16.f32 "                   \
        "{%0,%1,%2,%3}, {%4,%5,%6,%7}, {%8,%9}, {%0,%1,%2,%3};"                \
        : "+f"((d)[0]), "+f"((d)[1]), "+f"((d)[2]), "+f"((d)[3])               \
        : "r"((a)[0]), "r"((a)[1]), "r"((a)[2]), "r"((a)[3]),                  \
          "r"(b0), "r"(b1))

// ---------------------------------------------------------------------------
// Fused prep: blocks [0,16384) -> A fragments, [16384,18432) -> B fragments.
// ---------------------------------------------------------------------------
__global__ __launch_bounds__(256) void prep_kernel(
    const float* __restrict__ x, const float* __restrict__ W,
    __half* __restrict__ Ap, __half* __restrict__ Bp)
{
    int t = threadIdx.x & 31;
    if (blockIdx.x < 16384) {
        int T = blockIdx.x * 8 + (threadIdx.x >> 5);
        int kt    = T & 1;
        int mt    = (T >> 1) & 7;
        int k_blk = (T >> 4) & 31;
        int m_blk = T >> 9;
        int r = m_blk * BM + mt * 16 + (t >> 2);
        int c = k_blk * 32 + kt * 16 + (t & 3) * 2;
        const float* xr = x + (size_t)r * K_DIM + c;
        float2 v0 = *(const float2*)xr;
        float2 v1 = *(const float2*)(xr + (size_t)8 * K_DIM);
        float2 v2 = *(const float2*)(xr + 8);
        float2 v3 = *(const float2*)(xr + (size_t)8 * K_DIM + 8);
        uint4 o;
        o.x = h2_u32(__floats2half2_rn(v0.x, v0.y));
        o.y = h2_u32(__floats2half2_rn(v1.x, v1.y));
        o.z = h2_u32(__floats2half2_rn(v2.x, v2.y));
        o.w = h2_u32(__floats2half2_rn(v3.x, v3.y));
        ((uint4*)Ap)[(size_t)T * 32 + t] = o;
    } else {
        int T = (blockIdx.x - 16384) * 8 + (threadIdx.x >> 5);
        int kt    = T & 1;
        int np    = (T >> 1) & 7;
        int k_blk = (T >> 4) & 31;
        int n_blk = T >> 9;
        int k = k_blk * 32 + kt * 16 + (t & 3) * 2;
        int n = n_blk * BN + np * 16 + (t >> 2);
        const float* wp = W + (size_t)k * N_DIM + n;
        float w0  = wp[0];
        float w1  = wp[N_DIM];
        float w8  = wp[(size_t)8 * N_DIM];
        float w9  = wp[(size_t)9 * N_DIM];
        float w0b = wp[8];
        float w1b = wp[N_DIM + 8];
        float w8b = wp[(size_t)8 * N_DIM + 8];
        float w9b = wp[(size_t)9 * N_DIM + 8];
        uint4 o;
        o.x = h2_u32(__floats2half2_rn(w0, w1));
        o.y = h2_u32(__floats2half2_rn(w8, w9));
        o.z = h2_u32(__floats2half2_rn(w0b, w1b));
        o.w = h2_u32(__floats2half2_rn(w8b, w9b));
        ((uint4*)Bp)[(size_t)T * 32 + t] = o;
    }
}

// ---------------------------------------------------------------------------
// GEMM: U16 = Ap . Bp^T via mma.sync m16n8k16 fp16 (fp32 accum).
// CTA 128x128, 4 warps (2x2), warp tile 64x64, BK=64, 3-stage cp.async,
// 2 CTAs/SM; fragment loads double-buffered across 4 k-substeps.
// ---------------------------------------------------------------------------
__global__ __launch_bounds__(128, 2) void gemm_f16_mma_kernel(
    const __half* __restrict__ Ap,
    const __half* __restrict__ Bp,
    __half* __restrict__ U16)
{
    extern __shared__ __align__(16) char smem[];
    const uint32_t sbase = smem_u32(smem);
    const int tid  = threadIdx.x;
    const int wid  = tid >> 5;
    const int lane = tid & 31;
    const int wr   = wid >> 1;     // 0..1: 64-row slab
    const int wc   = wid & 1;      // 0..1: 64-col slab
    const int mb   = blockIdx.y;
    const int nb   = blockIdx.x;

    const char* gA = (const char*)(Ap) + (size_t)mb * NSTG * ASTG_B;
    const char* gB = (const char*)(Bp) + (size_t)nb * NSTG * BSTG_B;

    auto load_stage = [&](int s) {
        uint32_t sa = sbase + (uint32_t)(s % NPIPE) * STG_B;
        const char* ga = gA + (size_t)s * ASTG_B;
        const char* gb = gB + (size_t)s * BSTG_B;
#pragma unroll
        for (int i = 0; i < 8; i++)
            cp16(sa + tid * 16 + i * 2048, ga + tid * 16 + i * 2048);
        uint32_t sb = sa + ASTG_B;
#pragma unroll
        for (int i = 0; i < 8; i++)
            cp16(sb + tid * 16 + i * 2048, gb + tid * 16 + i * 2048);
        asm volatile("cp.async.commit_group;" ::: "memory");
    };

    load_stage(0);
    load_stage(1);

    float acc[4][8][4] = {};
    uint32_t afr[2][4][4];
    uint32_t bfr[2][4][4];

    const uint32_t aoff = (uint32_t)((wr * 4) * 2 * 32 + lane) * 16;  // +mi*1024 +kt*512
    const uint32_t boff = (uint32_t)((wc * 4) * 2 * 32 + lane) * 16;  // +pi*1024 +kt*512

    for (int kb = 0; kb < NSTG; kb++) {
        if (kb < NSTG - 1) asm volatile("cp.async.wait_group 1;" ::: "memory");
        else               asm volatile("cp.async.wait_group 0;" ::: "memory");
        __syncthreads();

        uint32_t sstage = sbase + (uint32_t)(kb % NPIPE) * STG_B;

        auto load_frags = [&](int kk, int buf) {
            uint32_t sa = sstage + (uint32_t)(kk >> 1) * 8192 + aoff
                        + (uint32_t)(kk & 1) * 512;
            uint32_t sb = sstage + ASTG_B + (uint32_t)(kk >> 1) * 8192 + boff
                        + (uint32_t)(kk & 1) * 512;
#pragma unroll
            for (int mi = 0; mi < 4; mi++)
                LDS128(afr[buf][mi][0], afr[buf][mi][1],
                       afr[buf][mi][2], afr[buf][mi][3], sa + mi * 1024);
#pragma unroll
            for (int pi = 0; pi < 4; pi++)
                LDS128(bfr[buf][pi][0], bfr[buf][pi][1],
                       bfr[buf][pi][2], bfr[buf][pi][3], sb + pi * 1024);
        };

        load_frags(0, 0);
        if (kb + 2 < NSTG) load_stage(kb + 2);

#pragma unroll
        for (int kk = 0; kk < 4; kk++) {
            int cur = kk & 1;
            if (kk < 3) load_frags(kk + 1, cur ^ 1);
#pragma unroll
            for (int mi = 0; mi < 4; mi++)
#pragma unroll
                for (int pi = 0; pi < 4; pi++) {
                    MMA_F16(acc[mi][pi * 2],     afr[cur][mi],
                            bfr[cur][pi][0], bfr[cur][pi][1]);
                    MMA_F16(acc[mi][pi * 2 + 1], afr[cur][mi],
                            bfr[cur][pi][2], bfr[cur][pi][3]);
                }
        }
    }

    // Epilogue: STG.64 packing (l even, l odd) for 2 gates; pairs acc[mi]
    // with acc[mi+2] (rows m and m+32 = same (b,d), consecutive l parity).
    {
        const int n  = nb * BN + wc * 64 + (lane & 3) * 2;  // +ni*8
        const int m0 = mb * BM + wr * 64 + (lane >> 2);
        const uint32_t goff = (uint32_t)(((n & 3) >> 1) * 8);
#pragma unroll
        for (int mi = 0; mi < 2; mi++) {
#pragma unroll
            for (int half = 0; half < 2; half++) {
                int m  = m0 + mi * 16 + half * 8;   // even-l row
                int l0 = m >> 5;
                int b  = m & 31;
                size_t ubase = (size_t)(l0 >> 1) * 32768 + (size_t)b * 1024;
#pragma unroll
                for (int ni = 0; ni < 8; ni++) {
                    int d = (n + ni * 8) >> 2;
                    uint2 v;
                    v.x = h2_u32(__floats2half2_rn(acc[mi][ni][half * 2],
                                                   acc[mi][ni][half * 2 + 1]));
                    v.y = h2_u32(__floats2half2_rn(acc[mi + 2][ni][half * 2],
                                                   acc[mi + 2][ni][half * 2 + 1]));
                    *(uint2*)((char*)U16 + (ubase + d) * 16 + goff) = v;
                }
            }
        }
    }
}

// ---------------------------------------------------------------------------
// SRU scan: one thread per (b,d) lane; HW tanh.approx for all gates.
// U16 unit = [g0l0 g1l0 g0l1 g1l1 g2l0 g3l0 g2l1 g3l1]; 16-deep prefetch.
// ---------------------------------------------------------------------------
__device__ __forceinline__ float tanh_fast(float x) {
    float r;
    asm("tanh.approx.f32 %0, %1;" : "=f"(r) : "f"(x));
    return r;
}
__device__ __forceinline__ float sigmoid_fast(float z) {
    return fmaf(tanh_fast(z * 0.5f), 0.5f, 0.5f);
}

__global__ __launch_bounds__(64) void sru_scan_kernel(
    const __half* __restrict__ U16,
    const float* __restrict__ c0,
    const float* __restrict__ V,
    const float* __restrict__ bias,
    float* __restrict__ h_out,
    float* __restrict__ c_out)
{
    const int t = blockIdx.x * blockDim.x + threadIdx.x;   // 0..32767 = b*1024+d
    const int d = t & (D_DIM - 1);

    const float vf = V[d];
    const float vr = V[D_DIM + d];
    const float bf = bias[d];
    const float br = bias[D_DIM + d];
    float c = c0[t];

    const uint4* __restrict__ Up = (const uint4*)U16 + t;  // stride 32768 per l-pair
    float* __restrict__ hp = h_out + t;

    uint4 buf[16];
#pragma unroll
    for (int j = 0; j < 16; j++) buf[j] = Up[(size_t)j * (B_DIM * D_DIM)];

    for (int lp = 0; lp < L_DIM / 2; lp += 16) {
        uint4 cur[16];
#pragma unroll
        for (int j = 0; j < 16; j++) cur[j] = buf[j];
        if (lp + 16 < L_DIM / 2) {
#pragma unroll
            for (int j = 0; j < 16; j++)
                buf[j] = Up[(size_t)(lp + 16 + j) * (B_DIM * D_DIM)];
        }
#pragma unroll
        for (int j = 0; j < 16; j++) {
            const __half2* hh = (const __half2*)&cur[j];
#pragma unroll
            for (int s = 0; s < 2; s++) {
                float2 g01 = __half22float2(hh[s]);       // {u0,u1} of l = 2lp+s
                float2 g23 = __half22float2(hh[2 + s]);   // {u2,u3}
                float f = sigmoid_fast(g01.y + c * vf + bf);
                float r = sigmoid_fast(g23.x + c * vr + br);
                c = g01.x + (c - g01.x) * f;
                float h = (tanh_fast(c) - g23.y) * r + g23.y;
                hp[(size_t)((lp + j) * 2 + s) * (B_DIM * D_DIM)] = h;
            }
        }
    }

    if (c_out) c_out[t] = c;
}

// ---------------------------------------------------------------------------
// Launch
// ---------------------------------------------------------------------------
extern "C" void kernel_launch(void* const* d_in, const int* in_sizes, int n_in,
                              void* d_out, int out_size)
{
    const float* x    = (const float*)d_in[0];   // (L,B,IN)
    const float* c0   = (const float*)d_in[1];   // (B,D)
    const float* W    = (const float*)d_in[2];   // (IN,4D)
    const float* V    = (const float*)d_in[3];   // (2D)
    const float* bias = (const float*)d_in[4];   // (2D)
    float* out = (float*)d_out;

    __half *U16 = nullptr, *Ap = nullptr, *Bp = nullptr;
    cudaGetSymbolAddress((void**)&U16, g_U16);
    cudaGetSymbolAddress((void**)&Ap, g_Ap);
    cudaGetSymbolAddress((void**)&Bp, g_Bp);

    cudaFuncSetAttribute(gemm_f16_mma_kernel,
                         cudaFuncAttributeMaxDynamicSharedMemorySize, GEMM_SMEM);

    prep_kernel<<<18432, 256>>>(x, W, Ap, Bp);

    gemm_f16_mma_kernel<<<dim3(N_DIM / BN, M_DIM / BM), 128, GEMM_SMEM>>>(
        Ap, Bp, U16);

    const size_t LBD = (size_t)L_DIM * B_DIM * D_DIM;
    float* c_out = ((size_t)out_size > LBD) ? (out + LBD) : nullptr;
    sru_scan_kernel<<<(B_DIM * D_DIM) / 64, 64>>>(U16, c0, V, bias, out, c_out);
}

// round 15
// speedup vs baseline: 1.1750x; 1.0973x over previous
#include <cuda_runtime.h>
#include <cuda_fp16.h>
#include <cstdint>

// ---------------------------------------------------------------------------
// Problem constants
// ---------------------------------------------------------------------------
#define L_DIM 1024
#define B_DIM 32
#define IN_DIM 1024
#define D_DIM 1024
#define M_DIM (L_DIM * B_DIM)      // 32768
#define N_DIM (4 * D_DIM)          // 4096
#define K_DIM IN_DIM               // 1024

// GEMM tiling (fp16 operands), 2 CTAs/SM, 4 warps/CTA, warp tile 64x64
#define BM 128
#define BN 128
#define BKB 64                     // K per stage
#define NSTG (K_DIM / BKB)         // 16 stages
#define ASTG_B (BM * BKB * 2)      // 16384 B / stage
#define BSTG_B (BN * BKB * 2)      // 16384 B / stage
#define STG_B (ASTG_B + BSTG_B)    // 32768 B
#define NPIPE 3
#define GEMM_SMEM (NPIPE * STG_B)  // 98304 B  -> 2 CTAs/SM

// Scratch (device globals; no allocation allowed)
// U stored fp16. 16B unit u = lp*32768 + b*1024 + d  (lp = l/2):
//   halves [g0l0 g1l0 g0l1 g1l1 g2l0 g3l0 g2l1 g3l1]
__device__ __half g_U16[(size_t)M_DIM * N_DIM];         // 256 MB
__device__ __half g_Ap[(size_t)M_DIM * K_DIM];          // 64 MB  fragment-ordered x
__device__ __half g_Bp[(size_t)N_DIM * K_DIM];          // 8 MB   fragment-ordered W

// ---------------------------------------------------------------------------
// helpers
// ---------------------------------------------------------------------------
__device__ __forceinline__ uint32_t smem_u32(const void* p) {
    uint32_t a;
    asm("{ .reg .u64 t; cvta.to.shared.u64 t, %1; cvt.u32.u64 %0, t; }"
        : "=r"(a) : "l"(p));
    return a;
}
__device__ __forceinline__ void cp16(uint32_t s, const void* g) {
    asm volatile("cp.async.cg.shared.global [%0], [%1], 16;" :: "r"(s), "l"(g));
}
__device__ __forceinline__ uint32_t h2_u32(__half2 h) {
    uint32_t u;
    memcpy(&u, &h, 4);
    return u;
}

#define LDS128(r0, r1, r2, r3, addr)                                           \
    asm volatile("ld.shared.v4.b32 {%0,%1,%2,%3}, [%4];"                       \
                 : "=r"(r0), "=r"(r1), "=r"(r2), "=r"(r3) : "r"(addr))

#define MMA_F16(d, a, b0, b1)                                                  \
    asm volatile(                                                              \
        "mma.sync.aligned.m16n8k16.row.col.f32.f16.f16.f32 "                   \
        "{%0,%1,%2,%3}, {%4,%5,%6,%7}, {%8,%9}, {%0,%1,%2,%3};"                \
        : "+f"((d)[0]), "+f"((d)[1]), "+f"((d)[2]), "+f"((d)[3])               \
        : "r"((a)[0]), "r"((a)[1]), "r"((a)[2]), "r"((a)[3]),                  \
          "r"(b0), "r"(b1))

// ---------------------------------------------------------------------------
// Fused prep: blocks [0,16384) -> A fragments, [16384,18432) -> B fragments.
// ---------------------------------------------------------------------------
__global__ __launch_bounds__(256) void prep_kernel(
    const float* __restrict__ x, const float* __restrict__ W,
    __half* __restrict__ Ap, __half* __restrict__ Bp)
{
    int t = threadIdx.x & 31;
    if (blockIdx.x < 16384) {
        int T = blockIdx.x * 8 + (threadIdx.x >> 5);
        int kt    = T & 1;
        int mt    = (T >> 1) & 7;
        int k_blk = (T >> 4) & 31;
        int m_blk = T >> 9;
        int r = m_blk * BM + mt * 16 + (t >> 2);
        int c = k_blk * 32 + kt * 16 + (t & 3) * 2;
        const float* xr = x + (size_t)r * K_DIM + c;
        float2 v0 = *(const float2*)xr;
        float2 v1 = *(const float2*)(xr + (size_t)8 * K_DIM);
        float2 v2 = *(const float2*)(xr + 8);
        float2 v3 = *(const float2*)(xr + (size_t)8 * K_DIM + 8);
        uint4 o;
        o.x = h2_u32(__floats2half2_rn(v0.x, v0.y));
        o.y = h2_u32(__floats2half2_rn(v1.x, v1.y));
        o.z = h2_u32(__floats2half2_rn(v2.x, v2.y));
        o.w = h2_u32(__floats2half2_rn(v3.x, v3.y));
        ((uint4*)Ap)[(size_t)T * 32 + t] = o;
    } else {
        int T = (blockIdx.x - 16384) * 8 + (threadIdx.x >> 5);
        int kt    = T & 1;
        int np    = (T >> 1) & 7;
        int k_blk = (T >> 4) & 31;
        int n_blk = T >> 9;
        int k = k_blk * 32 + kt * 16 + (t & 3) * 2;
        int n = n_blk * BN + np * 16 + (t >> 2);
        const float* wp = W + (size_t)k * N_DIM + n;
        float w0  = wp[0];
        float w1  = wp[N_DIM];
        float w8  = wp[(size_t)8 * N_DIM];
        float w9  = wp[(size_t)9 * N_DIM];
        float w0b = wp[8];
        float w1b = wp[N_DIM + 8];
        float w8b = wp[(size_t)8 * N_DIM + 8];
        float w9b = wp[(size_t)9 * N_DIM + 8];
        uint4 o;
        o.x = h2_u32(__floats2half2_rn(w0, w1));
        o.y = h2_u32(__floats2half2_rn(w8, w9));
        o.z = h2_u32(__floats2half2_rn(w0b, w1b));
        o.w = h2_u32(__floats2half2_rn(w8b, w9b));
        ((uint4*)Bp)[(size_t)T * 32 + t] = o;
    }
}

// ---------------------------------------------------------------------------
// GEMM: U16 = Ap . Bp^T via mma.sync m16n8k16 fp16 (fp32 accum).
// CTA 128x128, 4 warps (2x2), warp tile 64x64, BK=64, 3-stage cp.async,
// 2 CTAs/SM; statically-scheduled mainloop (unroll-3, constant buffers).
// ---------------------------------------------------------------------------
__global__ __launch_bounds__(128, 2) void gemm_f16_mma_kernel(
    const __half* __restrict__ Ap,
    const __half* __restrict__ Bp,
    __half* __restrict__ U16)
{
    extern __shared__ __align__(16) char smem[];
    const uint32_t sbase = smem_u32(smem);
    const int tid  = threadIdx.x;
    const int wid  = tid >> 5;
    const int lane = tid & 31;
    const int wr   = wid >> 1;     // 0..1: 64-row slab
    const int wc   = wid & 1;      // 0..1: 64-col slab
    const int mb   = blockIdx.y;
    const int nb   = blockIdx.x;

    const char* gA = (const char*)(Ap) + (size_t)mb * NSTG * ASTG_B;
    const char* gB = (const char*)(Bp) + (size_t)nb * NSTG * BSTG_B;

    auto load_stage = [&](int s, uint32_t buf) {
        uint32_t sa = sbase + buf * STG_B;
        const char* ga = gA + (size_t)s * ASTG_B;
        const char* gb = gB + (size_t)s * BSTG_B;
#pragma unroll
        for (int i = 0; i < 8; i++)
            cp16(sa + tid * 16 + i * 2048, ga + tid * 16 + i * 2048);
        uint32_t sb = sa + ASTG_B;
#pragma unroll
        for (int i = 0; i < 8; i++)
            cp16(sb + tid * 16 + i * 2048, gb + tid * 16 + i * 2048);
        asm volatile("cp.async.commit_group;" ::: "memory");
    };

    load_stage(0, 0);
    load_stage(1, 1);

    float acc[4][8][4] = {};
    uint32_t afr[2][4][4];
    uint32_t bfr[2][4][4];

    const uint32_t aoff = (uint32_t)((wr * 4) * 2 * 32 + lane) * 16;  // +mi*1024 +kt*512
    const uint32_t boff = (uint32_t)((wc * 4) * 2 * 32 + lane) * 16;  // +pi*1024 +kt*512

    auto load_frags = [&](uint32_t sstage, int kk, int buf) {
        uint32_t sa = sstage + (uint32_t)(kk >> 1) * 8192 + aoff
                    + (uint32_t)(kk & 1) * 512;
        uint32_t sb = sstage + ASTG_B + (uint32_t)(kk >> 1) * 8192 + boff
                    + (uint32_t)(kk & 1) * 512;
#pragma unroll
        for (int mi = 0; mi < 4; mi++)
            LDS128(afr[buf][mi][0], afr[buf][mi][1],
                   afr[buf][mi][2], afr[buf][mi][3], sa + mi * 1024);
#pragma unroll
        for (int pi = 0; pi < 4; pi++)
            LDS128(bfr[buf][pi][0], bfr[buf][pi][1],
                   bfr[buf][pi][2], bfr[buf][pi][3], sb + pi * 1024);
    };

    auto do_substeps = [&](uint32_t sstage) {
        load_frags(sstage, 0, 0);
#pragma unroll
        for (int kk = 0; kk < 4; kk++) {
            int cur = kk & 1;
            if (kk < 3) load_frags(sstage, kk + 1, cur ^ 1);
#pragma unroll
            for (int mi = 0; mi < 4; mi++)
#pragma unroll
                for (int pi = 0; pi < 4; pi++) {
                    MMA_F16(acc[mi][pi * 2],     afr[cur][mi],
                            bfr[cur][pi][0], bfr[cur][pi][1]);
                    MMA_F16(acc[mi][pi * 2 + 1], afr[cur][mi],
                            bfr[cur][pi][2], bfr[cur][pi][3]);
                }
        }
    };

    // stages 0..14: constant wait_group 1; unroll by 3 so kb%3 folds.
#pragma unroll 3
    for (int kb = 0; kb < NSTG - 1; kb++) {
        asm volatile("cp.async.wait_group 1;" ::: "memory");
        __syncthreads();
        uint32_t buf = (uint32_t)(kb % NPIPE);
        uint32_t sstage = sbase + buf * STG_B;
        // issue next-stage global loads right after the first frag batch
        load_frags(sstage, 0, 0);
        if (kb < NSTG - 2)
            load_stage(kb + 2, (uint32_t)((kb + 2) % NPIPE));
#pragma unroll
        for (int kk = 0; kk < 4; kk++) {
            int cur = kk & 1;
            if (kk < 3) load_frags(sstage, kk + 1, cur ^ 1);
#pragma unroll
            for (int mi = 0; mi < 4; mi++)
#pragma unroll
                for (int pi = 0; pi < 4; pi++) {
                    MMA_F16(acc[mi][pi * 2],     afr[cur][mi],
                            bfr[cur][pi][0], bfr[cur][pi][1]);
                    MMA_F16(acc[mi][pi * 2 + 1], afr[cur][mi],
                            bfr[cur][pi][2], bfr[cur][pi][3]);
                }
        }
    }
    // final stage (15): buffer 0, wait all
    {
        asm volatile("cp.async.wait_group 0;" ::: "memory");
        __syncthreads();
        do_substeps(sbase + (uint32_t)((NSTG - 1) % NPIPE) * STG_B);
    }

    // Epilogue: STG.64 packing (l even, l odd) for 2 gates; pairs acc[mi]
    // with acc[mi+2] (rows m and m+32 = same (b,d), consecutive l parity).
    {
        const int n  = nb * BN + wc * 64 + (lane & 3) * 2;  // +ni*8
        const int m0 = mb * BM + wr * 64 + (lane >> 2);
        const uint32_t goff = (uint32_t)(((n & 3) >> 1) * 8);
#pragma unroll
        for (int mi = 0; mi < 2; mi++) {
#pragma unroll
            for (int half = 0; half < 2; half++) {
                int m  = m0 + mi * 16 + half * 8;   // even-l row
                int l0 = m >> 5;
                int b  = m & 31;
                size_t ubase = (size_t)(l0 >> 1) * 32768 + (size_t)b * 1024;
#pragma unroll
                for (int ni = 0; ni < 8; ni++) {
                    int d = (n + ni * 8) >> 2;
                    uint2 v;
                    v.x = h2_u32(__floats2half2_rn(acc[mi][ni][half * 2],
                                                   acc[mi][ni][half * 2 + 1]));
                    v.y = h2_u32(__floats2half2_rn(acc[mi + 2][ni][half * 2],
                                                   acc[mi + 2][ni][half * 2 + 1]));
                    *(uint2*)((char*)U16 + (ubase + d) * 16 + goff) = v;
                }
            }
        }
    }
}

// ---------------------------------------------------------------------------
// SRU scan: one thread per (b,d) lane; HW tanh.approx for all gates.
// U16 unit = [g0l0 g1l0 g0l1 g1l1 g2l0 g3l0 g2l1 g3l1]; 16-deep prefetch.
// ---------------------------------------------------------------------------
__device__ __forceinline__ float tanh_fast(float x) {
    float r;
    asm("tanh.approx.f32 %0, %1;" : "=f"(r) : "f"(x));
    return r;
}
__device__ __forceinline__ float sigmoid_fast(float z) {
    return fmaf(tanh_fast(z * 0.5f), 0.5f, 0.5f);
}

__global__ __launch_bounds__(64) void sru_scan_kernel(
    const __half* __restrict__ U16,
    const float* __restrict__ c0,
    const float* __restrict__ V,
    const float* __restrict__ bias,
    float* __restrict__ h_out,
    float* __restrict__ c_out)
{
    const int t = blockIdx.x * blockDim.x + threadIdx.x;   // 0..32767 = b*1024+d
    const int d = t & (D_DIM - 1);

    const float vf = V[d];
    const float vr = V[D_DIM + d];
    const float bf = bias[d];
    const float br = bias[D_DIM + d];
    float c = c0[t];

    const uint4* __restrict__ Up = (const uint4*)U16 + t;  // bumped by 16*32768
    const uint4* __restrict__ Upl = Up;                    // prefetch cursor
    float* __restrict__ hp = h_out + t;

    uint4 buf[16];
#pragma unroll
    for (int j = 0; j < 16; j++) buf[j] = Upl[(size_t)j * (B_DIM * D_DIM)];
    Upl += (size_t)16 * (B_DIM * D_DIM);

    for (int lp = 0; lp < L_DIM / 2; lp += 16) {
        uint4 cur[16];
#pragma unroll
        for (int j = 0; j < 16; j++) cur[j] = buf[j];
        if (lp + 16 < L_DIM / 2) {
#pragma unroll
            for (int j = 0; j < 16; j++)
                buf[j] = Upl[(size_t)j * (B_DIM * D_DIM)];
            Upl += (size_t)16 * (B_DIM * D_DIM);
        }
#pragma unroll
        for (int j = 0; j < 16; j++) {
            const __half2* hh = (const __half2*)&cur[j];
#pragma unroll
            for (int s = 0; s < 2; s++) {
                float2 g01 = __half22float2(hh[s]);       // {u0,u1} of l = 2lp+s
                float2 g23 = __half22float2(hh[2 + s]);   // {u2,u3}
                float f = sigmoid_fast(g01.y + c * vf + bf);
                float r = sigmoid_fast(g23.x + c * vr + br);
                c = g01.x + (c - g01.x) * f;
                float h = (tanh_fast(c) - g23.y) * r + g23.y;
                hp[(size_t)((lp + j) * 2 + s) * (B_DIM * D_DIM)] = h;
            }
        }
    }

    if (c_out) c_out[t] = c;
}

// ---------------------------------------------------------------------------
// Launch
// ---------------------------------------------------------------------------
extern "C" void kernel_launch(void* const* d_in, const int* in_sizes, int n_in,
                              void* d_out, int out_size)
{
    const float* x    = (const float*)d_in[0];   // (L,B,IN)
    const float* c0   = (const float*)d_in[1];   // (B,D)
    const float* W    = (const float*)d_in[2];   // (IN,4D)
    const float* V    = (const float*)d_in[3];   // (2D)
    const float* bias = (const float*)d_in[4];   // (2D)
    float* out = (float*)d_out;

    __half *U16 = nullptr, *Ap = nullptr, *Bp = nullptr;
    cudaGetSymbolAddress((void**)&U16, g_U16);
    cudaGetSymbolAddress((void**)&Ap, g_Ap);
    cudaGetSymbolAddress((void**)&Bp, g_Bp);

    cudaFuncSetAttribute(gemm_f16_mma_kernel,
                         cudaFuncAttributeMaxDynamicSharedMemorySize, GEMM_SMEM);

    prep_kernel<<<18432, 256>>>(x, W, Ap, Bp);

    gemm_f16_mma_kernel<<<dim3(N_DIM / BN, M_DIM / BM), 128, GEMM_SMEM>>>(
        Ap, Bp, U16);

    const size_t LBD = (size_t)L_DIM * B_DIM * D_DIM;
    float* c_out = ((size_t)out_size > LBD) ? (out + LBD) : nullptr;
    sru_scan_kernel<<<(B_DIM * D_DIM) / 64, 64>>>(U16, c0, V, bias, out, c_out);
}

// round 16
// speedup vs baseline: 1.2205x; 1.0387x over previous
#include <cuda_runtime.h>
#include <cuda_fp16.h>
#include <cstdint>

// ---------------------------------------------------------------------------
// Problem constants
// ---------------------------------------------------------------------------
#define L_DIM 1024
#define B_DIM 32
#define IN_DIM 1024
#define D_DIM 1024
#define M_DIM (L_DIM * B_DIM)      // 32768
#define N_DIM (4 * D_DIM)          // 4096
#define K_DIM IN_DIM               // 1024

// GEMM tiling (fp16 operands), 2 CTAs/SM, 4 warps/CTA, warp tile 64x64
#define BM 128
#define BN 128
#define BKB 64                     // K per stage
#define NSTG (K_DIM / BKB)         // 16 stages
#define ASTG_B (BM * BKB * 2)      // 16384 B / stage
#define BSTG_B (BN * BKB * 2)      // 16384 B / stage
#define STG_B (ASTG_B + BSTG_B)    // 32768 B
#define NPIPE 3
#define MBAR_OFF (NPIPE * STG_B)            // 98304
#define GEMM_SMEM (MBAR_OFF + 128)          // mbarriers + pad -> 2 CTAs/SM

// Scratch (device globals; no allocation allowed)
// U stored fp16. 16B unit u = lp*32768 + b*1024 + d  (lp = l/2):
//   halves [g0l0 g1l0 g0l1 g1l1 g2l0 g3l0 g2l1 g3l1]
__device__ __half g_U16[(size_t)M_DIM * N_DIM];         // 256 MB
__device__ __half g_Ap[(size_t)M_DIM * K_DIM];          // 64 MB  fragment-ordered x
__device__ __half g_Bp[(size_t)N_DIM * K_DIM];          // 8 MB   fragment-ordered W

// ---------------------------------------------------------------------------
// helpers
// ---------------------------------------------------------------------------
__device__ __forceinline__ uint32_t smem_u32(const void* p) {
    uint32_t a;
    asm("{ .reg .u64 t; cvta.to.shared.u64 t, %1; cvt.u32.u64 %0, t; }"
        : "=r"(a) : "l"(p));
    return a;
}
__device__ __forceinline__ uint32_t h2_u32(__half2 h) {
    uint32_t u;
    memcpy(&u, &h, 4);
    return u;
}
__device__ __forceinline__ void mbar_init(uint32_t a, uint32_t cnt) {
    asm volatile("mbarrier.init.shared.b64 [%0], %1;" :: "r"(a), "r"(cnt) : "memory");
}
__device__ __forceinline__ void mbar_arrive(uint32_t a) {
    asm volatile("mbarrier.arrive.shared.b64 _, [%0];" :: "r"(a) : "memory");
}
__device__ __forceinline__ void mbar_expect_tx(uint32_t a, uint32_t bytes) {
    asm volatile("mbarrier.arrive.expect_tx.shared.b64 _, [%0], %1;"
                 :: "r"(a), "r"(bytes) : "memory");
}
__device__ __forceinline__ void mbar_wait(uint32_t a, uint32_t ph) {
    asm volatile(
        "{\n\t.reg .pred P;\n"
        "W%=:\n\t"
        "mbarrier.try_wait.parity.acquire.cta.shared::cta.b64 P, [%0], %1, 0x989680;\n\t"
        "@!P bra W%=;\n\t}"
        :: "r"(a), "r"(ph) : "memory");
}
__device__ __forceinline__ void mbar_wait_relaxed(uint32_t a, uint32_t ph) {
    asm volatile(
        "{\n\t.reg .pred P;\n"
        "W%=:\n\t"
        "mbarrier.try_wait.parity.relaxed.cta.shared::cta.b64 P, [%0], %1, 0x989680;\n\t"
        "@!P bra W%=;\n\t}"
        :: "r"(a), "r"(ph) : "memory");
}
__device__ __forceinline__ void bulk_g2s(uint32_t dst, const void* src,
                                         uint32_t bytes, uint32_t mbar) {
    asm volatile(
        "cp.async.bulk.shared::cta.global.mbarrier::complete_tx::bytes "
        "[%0], [%1], %2, [%3];"
        :: "r"(dst), "l"(src), "r"(bytes), "r"(mbar) : "memory");
}

#define LDS128(r0, r1, r2, r3, addr)                                           \
    asm volatile("ld.shared.v4.b32 {%0,%1,%2,%3}, [%4];"                       \
                 : "=r"(r0), "=r"(r1), "=r"(r2), "=r"(r3) : "r"(addr))

#define MMA_F16(d, a, b0, b1)                                                  \
    asm volatile(                                                              \
        "mma.sync.aligned.m16n8k16.row.col.f32.f16.f16.f32 "                   \
        "{%0,%1,%2,%3}, {%4,%5,%6,%7}, {%8,%9}, {%0,%1,%2,%3};"                \
        : "+f"((d)[0]), "+f"((d)[1]), "+f"((d)[2]), "+f"((d)[3])               \
        : "r"((a)[0]), "r"((a)[1]), "r"((a)[2]), "r"((a)[3]),                  \
          "r"(b0), "r"(b1))

// ---------------------------------------------------------------------------
// Fused prep: blocks [0,16384) -> A fragments, [16384,18432) -> B fragments.
// ---------------------------------------------------------------------------
__global__ __launch_bounds__(256) void prep_kernel(
    const float* __restrict__ x, const float* __restrict__ W,
    __half* __restrict__ Ap, __half* __restrict__ Bp)
{
    int t = threadIdx.x & 31;
    if (blockIdx.x < 16384) {
        int T = blockIdx.x * 8 + (threadIdx.x >> 5);
        int kt    = T & 1;
        int mt    = (T >> 1) & 7;
        int k_blk = (T >> 4) & 31;
        int m_blk = T >> 9;
        int r = m_blk * BM + mt * 16 + (t >> 2);
        int c = k_blk * 32 + kt * 16 + (t & 3) * 2;
        const float* xr = x + (size_t)r * K_DIM + c;
        float2 v0 = *(const float2*)xr;
        float2 v1 = *(const float2*)(xr + (size_t)8 * K_DIM);
        float2 v2 = *(const float2*)(xr + 8);
        float2 v3 = *(const float2*)(xr + (size_t)8 * K_DIM + 8);
        uint4 o;
        o.x = h2_u32(__floats2half2_rn(v0.x, v0.y));
        o.y = h2_u32(__floats2half2_rn(v1.x, v1.y));
        o.z = h2_u32(__floats2half2_rn(v2.x, v2.y));
        o.w = h2_u32(__floats2half2_rn(v3.x, v3.y));
        ((uint4*)Ap)[(size_t)T * 32 + t] = o;
    } else {
        int T = (blockIdx.x - 16384) * 8 + (threadIdx.x >> 5);
        int kt    = T & 1;
        int np    = (T >> 1) & 7;
        int k_blk = (T >> 4) & 31;
        int n_blk = T >> 9;
        int k = k_blk * 32 + kt * 16 + (t & 3) * 2;
        int n = n_blk * BN + np * 16 + (t >> 2);
        const float* wp = W + (size_t)k * N_DIM + n;
        float w0  = wp[0];
        float w1  = wp[N_DIM];
        float w8  = wp[(size_t)8 * N_DIM];
        float w9  = wp[(size_t)9 * N_DIM];
        float w0b = wp[8];
        float w1b = wp[N_DIM + 8];
        float w8b = wp[(size_t)8 * N_DIM + 8];
        float w9b = wp[(size_t)9 * N_DIM + 8];
        uint4 o;
        o.x = h2_u32(__floats2half2_rn(w0, w1));
        o.y = h2_u32(__floats2half2_rn(w8, w9));
        o.z = h2_u32(__floats2half2_rn(w0b, w1b));
        o.w = h2_u32(__floats2half2_rn(w8b, w9b));
        ((uint4*)Bp)[(size_t)T * 32 + t] = o;
    }
}

// ---------------------------------------------------------------------------
// GEMM: U16 = Ap . Bp^T via mma.sync m16n8k16 fp16 (fp32 accum).
// CTA 128x128, 4 warps (2x2), warp tile 64x64, BK=64, 3-stage ring,
// single-thread cp.async.bulk producer + mbarrier full/empty signaling.
// No __syncthreads in the mainloop.
// ---------------------------------------------------------------------------
__global__ __launch_bounds__(128, 2) void gemm_f16_mma_kernel(
    const __half* __restrict__ Ap,
    const __half* __restrict__ Bp,
    __half* __restrict__ U16)
{
    extern __shared__ __align__(1024) char smem[];
    const uint32_t sbase = smem_u32(smem);
    const uint32_t mbase = sbase + MBAR_OFF;   // full[3] then empty[3]
    const int tid  = threadIdx.x;
    const int wid  = tid >> 5;
    const int lane = tid & 31;
    const int wr   = wid >> 1;     // 0..1: 64-row slab
    const int wc   = wid & 1;      // 0..1: 64-col slab
    const int mb   = blockIdx.y;
    const int nb   = blockIdx.x;

    const char* gA = (const char*)(Ap) + (size_t)mb * NSTG * ASTG_B;
    const char* gB = (const char*)(Bp) + (size_t)nb * NSTG * BSTG_B;

    if (tid == 0) {
#pragma unroll
        for (int s = 0; s < NPIPE; s++) {
            mbar_init(mbase + s * 8, 1);            // full[s]: 1 expect-arrive
            mbar_init(mbase + 24 + s * 8, 128);     // empty[s]: all threads
        }
    }
    __syncthreads();

    // producer: issue stage p (buffer p%3) after its empty phase
    auto produce = [&](int p) {
        uint32_t b    = (uint32_t)(p % NPIPE);
        uint32_t full = mbase + b * 8;
        // empty cursor starts at phase 1 -> first NPIPE waits pass instantly
        mbar_wait_relaxed(mbase + 24 + b * 8, 1u ^ (uint32_t)((p / NPIPE) & 1));
        mbar_expect_tx(full, (uint32_t)STG_B);
        uint32_t sa = sbase + b * STG_B;
        bulk_g2s(sa, gA + (size_t)p * ASTG_B, (uint32_t)ASTG_B, full);
        bulk_g2s(sa + ASTG_B, gB + (size_t)p * BSTG_B, (uint32_t)BSTG_B, full);
    };

    if (tid == 0) { produce(0); produce(1); }

    float acc[4][8][4] = {};
    uint32_t afr[2][4][4];
    uint32_t bfr[2][4][4];

    const uint32_t aoff = (uint32_t)((wr * 4) * 2 * 32 + lane) * 16;  // +mi*1024 +kt*512
    const uint32_t boff = (uint32_t)((wc * 4) * 2 * 32 + lane) * 16;  // +pi*1024 +kt*512

    auto load_frags = [&](uint32_t sstage, int kk, int buf) {
        uint32_t sa = sstage + (uint32_t)(kk >> 1) * 8192 + aoff
                    + (uint32_t)(kk & 1) * 512;
        uint32_t sb = sstage + ASTG_B + (uint32_t)(kk >> 1) * 8192 + boff
                    + (uint32_t)(kk & 1) * 512;
#pragma unroll
        for (int mi = 0; mi < 4; mi++)
            LDS128(afr[buf][mi][0], afr[buf][mi][1],
                   afr[buf][mi][2], afr[buf][mi][3], sa + mi * 1024);
#pragma unroll
        for (int pi = 0; pi < 4; pi++)
            LDS128(bfr[buf][pi][0], bfr[buf][pi][1],
                   bfr[buf][pi][2], bfr[buf][pi][3], sb + pi * 1024);
    };

    auto consume_stage = [&](int s) {
        uint32_t b = (uint32_t)(s % NPIPE);
        mbar_wait(mbase + b * 8, (uint32_t)((s / NPIPE) & 1));
        uint32_t sstage = sbase + b * STG_B;
        load_frags(sstage, 0, 0);
#pragma unroll
        for (int kk = 0; kk < 4; kk++) {
            int cur = kk & 1;
            if (kk < 3) load_frags(sstage, kk + 1, cur ^ 1);
#pragma unroll
            for (int mi = 0; mi < 4; mi++)
#pragma unroll
                for (int pi = 0; pi < 4; pi++) {
                    MMA_F16(acc[mi][pi * 2],     afr[cur][mi],
                            bfr[cur][pi][0], bfr[cur][pi][1]);
                    MMA_F16(acc[mi][pi * 2 + 1], afr[cur][mi],
                            bfr[cur][pi][2], bfr[cur][pi][3]);
                }
        }
        mbar_arrive(mbase + 24 + b * 8);   // release buffer b
    };

    // stages 0..13 produce s+2 first (overlap), unroll 3 folds b = s%3
#pragma unroll 3
    for (int s = 0; s < NSTG - 2; s++) {     // 14 iters: remainder handled fine
        if (tid == 0) produce(s + 2);
        consume_stage(s);
    }
    consume_stage(NSTG - 2);
    consume_stage(NSTG - 1);

    // Epilogue: STG.64 packing (l even, l odd) for 2 gates; pairs acc[mi]
    // with acc[mi+2] (rows m and m+32 = same (b,d), consecutive l parity).
    {
        const int n  = nb * BN + wc * 64 + (lane & 3) * 2;  // +ni*8
        const int m0 = mb * BM + wr * 64 + (lane >> 2);
        const uint32_t goff = (uint32_t)(((n & 3) >> 1) * 8);
#pragma unroll
        for (int mi = 0; mi < 2; mi++) {
#pragma unroll
            for (int half = 0; half < 2; half++) {
                int m  = m0 + mi * 16 + half * 8;   // even-l row
                int l0 = m >> 5;
                int b  = m & 31;
                size_t ubase = (size_t)(l0 >> 1) * 32768 + (size_t)b * 1024;
#pragma unroll
                for (int ni = 0; ni < 8; ni++) {
                    int d = (n + ni * 8) >> 2;
                    uint2 v;
                    v.x = h2_u32(__floats2half2_rn(acc[mi][ni][half * 2],
                                                   acc[mi][ni][half * 2 + 1]));
                    v.y = h2_u32(__floats2half2_rn(acc[mi + 2][ni][half * 2],
                                                   acc[mi + 2][ni][half * 2 + 1]));
                    *(uint2*)((char*)U16 + (ubase + d) * 16 + goff) = v;
                }
            }
        }
    }
}

// ---------------------------------------------------------------------------
// SRU scan: one thread per (b,d) lane; HW tanh.approx for all gates.
// U16 unit = [g0l0 g1l0 g0l1 g1l1 g2l0 g3l0 g2l1 g3l1]; 16-deep prefetch.
// Grid 1024 x 32 for even SM load balance.
// ---------------------------------------------------------------------------
__device__ __forceinline__ float tanh_fast(float x) {
    float r;
    asm("tanh.approx.f32 %0, %1;" : "=f"(r) : "f"(x));
    return r;
}
__device__ __forceinline__ float sigmoid_fast(float z) {
    return fmaf(tanh_fast(z * 0.5f), 0.5f, 0.5f);
}

__global__ __launch_bounds__(32) void sru_scan_kernel(
    const __half* __restrict__ U16,
    const float* __restrict__ c0,
    const float* __restrict__ V,
    const float* __restrict__ bias,
    float* __restrict__ h_out,
    float* __restrict__ c_out)
{
    const int t = blockIdx.x * blockDim.x + threadIdx.x;   // 0..32767 = b*1024+d
    const int d = t & (D_DIM - 1);

    const float vf = V[d];
    const float vr = V[D_DIM + d];
    const float bf = bias[d];
    const float br = bias[D_DIM + d];
    float c = c0[t];

    const uint4* __restrict__ Upl = (const uint4*)U16 + t;  // prefetch cursor
    float* __restrict__ hp = h_out + t;

    uint4 buf[16];
#pragma unroll
    for (int j = 0; j < 16; j++) buf[j] = Upl[(size_t)j * (B_DIM * D_DIM)];
    Upl += (size_t)16 * (B_DIM * D_DIM);

    for (int lp = 0; lp < L_DIM / 2; lp += 16) {
        uint4 cur[16];
#pragma unroll
        for (int j = 0; j < 16; j++) cur[j] = buf[j];
        if (lp + 16 < L_DIM / 2) {
#pragma unroll
            for (int j = 0; j < 16; j++)
                buf[j] = Upl[(size_t)j * (B_DIM * D_DIM)];
            Upl += (size_t)16 * (B_DIM * D_DIM);
        }
#pragma unroll
        for (int j = 0; j < 16; j++) {
            const __half2* hh = (const __half2*)&cur[j];
#pragma unroll
            for (int s = 0; s < 2; s++) {
                float2 g01 = __half22float2(hh[s]);       // {u0,u1} of l = 2lp+s
                float2 g23 = __half22float2(hh[2 + s]);   // {u2,u3}
                float f = sigmoid_fast(g01.y + c * vf + bf);
                float r = sigmoid_fast(g23.x + c * vr + br);
                c = g01.x + (c - g01.x) * f;
                float h = (tanh_fast(c) - g23.y) * r + g23.y;
                hp[(size_t)((lp + j) * 2 + s) * (B_DIM * D_DIM)] = h;
            }
        }
    }

    if (c_out) c_out[t] = c;
}

// ---------------------------------------------------------------------------
// Launch
// ---------------------------------------------------------------------------
extern "C" void kernel_launch(void* const* d_in, const int* in_sizes, int n_in,
                              void* d_out, int out_size)
{
    const float* x    = (const float*)d_in[0];   // (L,B,IN)
    const float* c0   = (const float*)d_in[1];   // (B,D)
    const float* W    = (const float*)d_in[2];   // (IN,4D)
    const float* V    = (const float*)d_in[3];   // (2D)
    const float* bias = (const float*)d_in[4];   // (2D)
    float* out = (float*)d_out;

    __half *U16 = nullptr, *Ap = nullptr, *Bp = nullptr;
    cudaGetSymbolAddress((void**)&U16, g_U16);
    cudaGetSymbolAddress((void**)&Ap, g_Ap);
    cudaGetSymbolAddress((void**)&Bp, g_Bp);

    cudaFuncSetAttribute(gemm_f16_mma_kernel,
                         cudaFuncAttributeMaxDynamicSharedMemorySize, GEMM_SMEM);

    prep_kernel<<<18432, 256>>>(x, W, Ap, Bp);

    gemm_f16_mma_kernel<<<dim3(N_DIM / BN, M_DIM / BM), 128, GEMM_SMEM>>>(
        Ap, Bp, U16);

    const size_t LBD = (size_t)L_DIM * B_DIM * D_DIM;
    float* c_out = ((size_t)out_size > LBD) ? (out + LBD) : nullptr;
    sru_scan_kernel<<<(B_DIM * D_DIM) / 32, 32>>>(U16, c0, V, bias, out, c_out);
}